// round 11
// baseline (speedup 1.0000x reference)
#include <cuda_runtime.h>
#include <cstdint>

#define NS   1024      // n_states
#define NT   8192      // T; NT-1 = 8191 steps
#define NO   256       // n_out
#define NBLK 32        // persistent blocks (fat blocks: fewer barrier participants)
#define NTHR 1024      // threads per block
#define RPB  32        // rows per block

// k-value buffers (6 rotating stages) + per-block release/acquire flags.
__device__ __align__(16) float g_k[6][NS];
#define FSTRIDE 32                      // 128B apart -> distinct L2 lines
__device__ unsigned int g_flag[NBLK * FSTRIDE];

__global__ void init_kernel() {
    int i = blockIdx.x * blockDim.x + threadIdx.x;   // 4*256 = 1024 = 32*32
    g_flag[i] = 0u;
}

// No-op pad launch: aligns ncu -s 5 -c 1 onto ode_kernel (4 launches/call).
__global__ void ncu_pad_kernel() {}

// Acquire-spin until producer flag >= sc. All 32 lanes of a warp poll the
// SAME address -> hardware-coalesced single line request per warp per sweep.
__device__ __forceinline__ void wait_flag(const unsigned int* f, unsigned sc) {
    unsigned v;
    do {
        asm volatile("ld.acquire.gpu.global.u32 %0, [%1];"
                     : "=r"(v) : "l"(f) : "memory");
    } while (v < sc);
}

__global__ void __launch_bounds__(NTHR, 1)
ode_kernel(const float* __restrict__ x0, const float* __restrict__ t,
           const float* __restrict__ A, float* __restrict__ xs)
{
    __shared__ float ty_sm[NS];
    __shared__ __align__(16) float kcol[RPB];

    const int tid = threadIdx.x;
    const int b   = blockIdx.x;
    const int w   = tid >> 5;        // warp = local row (0..31)
    const int l   = tid & 31;
    const int R   = b * RPB + w;     // global row this warp produces
    // Thread owns state index tid; its producer block = tid/32 = w (uniform
    // across the warp -> coalesced broadcast poll).
    const unsigned int* myflag = &g_flag[w * FSTRIDE];

    const float dt = __ldg(&t[1]) - __ldg(&t[0]);

    float a[32];
#pragma unroll
    for (int i = 0; i < 32; i++) a[i] = __ldg(&A[R * NS + l + 32 * i]);

    float xr = __ldg(&x0[tid]);
    float k0, k1, k2, k3, k4, k5;

    if (w == b) xs[tid] = xr;        // xs row 0 = x0 (block b owns 32b..32b+31)

    unsigned sc = 0;   // monotonic stage counter

    // tanh -> ty_sm; BAR; matvec; warp reduce; lane0 -> kcol; BAR;
    // thread0 alone: store 32 k values (one 128B line) then release flag.
#define STAGE_BODY(Y) do {                                                  \
        ty_sm[tid] = tanhf(Y);                                              \
        __syncthreads();                                                    \
        float acc0 = 0.f, acc1 = 0.f, acc2 = 0.f, acc3 = 0.f;               \
        _Pragma("unroll")                                                   \
        for (int i = 0; i < 32; i += 4) {                                   \
            acc0 = fmaf(a[i + 0], ty_sm[l + 32 * (i + 0)], acc0);           \
            acc1 = fmaf(a[i + 1], ty_sm[l + 32 * (i + 1)], acc1);           \
            acc2 = fmaf(a[i + 2], ty_sm[l + 32 * (i + 2)], acc2);           \
            acc3 = fmaf(a[i + 3], ty_sm[l + 32 * (i + 3)], acc3);           \
        }                                                                   \
        float acc = (acc0 + acc1) + (acc2 + acc3);                          \
        _Pragma("unroll")                                                   \
        for (int o = 16; o > 0; o >>= 1)                                    \
            acc += __shfl_down_sync(0xffffffffu, acc, o);                   \
        if (l == 0) kcol[w] = acc;                                          \
        __syncthreads();                                                    \
        sc++;                                                               \
        if (tid == 0) {                                                     \
            int S = (int)((sc - 1) % 6u);                                   \
            _Pragma("unroll")                                               \
            for (int q = 0; q < 8; q++) {                                   \
                float4 v = *reinterpret_cast<float4*>(&kcol[q * 4]);        \
                *reinterpret_cast<float4*>(&g_k[S][b * RPB + q * 4]) = v;   \
            }                                                               \
            asm volatile("st.release.gpu.global.u32 [%0], %1;"              \
                         :: "l"(&g_flag[b * FSTRIDE]), "r"(sc) : "memory"); \
        }                                                                   \
    } while (0)

#define LOADK(KR, S) do {                                                   \
        wait_flag(myflag, sc);                                              \
        KR = __ldcg(&g_k[S][tid]);                                          \
    } while (0)

    for (int step = 0; step < NT - 1; step++) {
        // stage 1: y = x
        STAGE_BODY(xr);

        // stage 2
        LOADK(k0, 0);
        STAGE_BODY(fmaf(dt, 0.2f * k0, xr));

        // stage 3
        LOADK(k1, 1);
        {
            float acc = (3.0f / 40.0f) * k0;
            acc = fmaf(9.0f / 40.0f, k1, acc);
            STAGE_BODY(fmaf(dt, acc, xr));
        }

        // stage 4
        LOADK(k2, 2);
        {
            float acc = (44.0f / 45.0f) * k0;
            acc = fmaf(-56.0f / 15.0f, k1, acc);
            acc = fmaf(32.0f / 9.0f,  k2, acc);
            STAGE_BODY(fmaf(dt, acc, xr));
        }

        // stage 5
        LOADK(k3, 3);
        {
            float acc = (19372.0f / 6561.0f) * k0;
            acc = fmaf(-25360.0f / 2187.0f, k1, acc);
            acc = fmaf(64448.0f / 6561.0f,  k2, acc);
            acc = fmaf(-212.0f / 729.0f,    k3, acc);
            STAGE_BODY(fmaf(dt, acc, xr));
        }

        // stage 6
        LOADK(k4, 4);
        {
            float acc = (9017.0f / 3168.0f) * k0;
            acc = fmaf(-355.0f / 33.0f,     k1, acc);
            acc = fmaf(46732.0f / 5247.0f,  k2, acc);
            acc = fmaf(49.0f / 176.0f,      k3, acc);
            acc = fmaf(-5103.0f / 18656.0f, k4, acc);
            STAGE_BODY(fmaf(dt, acc, xr));
        }

        // x update
        LOADK(k5, 5);
        {
            float acc = (35.0f / 384.0f) * k0;
            acc = fmaf(500.0f / 1113.0f,   k2, acc);
            acc = fmaf(125.0f / 192.0f,    k3, acc);
            acc = fmaf(-2187.0f / 6784.0f, k4, acc);
            acc = fmaf(11.0f / 84.0f,      k5, acc);
            xr = fmaf(dt, acc, xr);
        }
        if (w == b) xs[(size_t)(step + 1) * NS + tid] = xr;
    }
#undef STAGE_BODY
#undef LOADK
}

// ---------------------------------------------------------------------------
// ys = xs @ C^T  (8192x1024 @ 1024x256) — 64x64 tiled fp32 GEMM.
// ---------------------------------------------------------------------------
__global__ void __launch_bounds__(256)
gemm_ys(const float* __restrict__ xs, const float* __restrict__ C,
        float* __restrict__ ys)
{
    const int BM = 64, BN = 64, BK = 16;
    __shared__ float As[BK][BM];
    __shared__ float Bs[BK][BN];

    const int tid = threadIdx.x;
    const int m0 = blockIdx.y * BM;
    const int n0 = blockIdx.x * BN;
    const int tx = tid & 15;
    const int ty = tid >> 4;

    const int lr = tid >> 2;
    const int lc = (tid & 3) * 4;

    float acc[4][4];
#pragma unroll
    for (int i = 0; i < 4; i++)
#pragma unroll
        for (int j = 0; j < 4; j++) acc[i][j] = 0.0f;

    for (int kk0 = 0; kk0 < NS; kk0 += BK) {
        float4 av = *reinterpret_cast<const float4*>(
            &xs[(size_t)(m0 + lr) * NS + kk0 + lc]);
        float4 bv = *reinterpret_cast<const float4*>(
            &C[(size_t)(n0 + lr) * NS + kk0 + lc]);
        As[lc + 0][lr] = av.x; As[lc + 1][lr] = av.y;
        As[lc + 2][lr] = av.z; As[lc + 3][lr] = av.w;
        Bs[lc + 0][lr] = bv.x; Bs[lc + 1][lr] = bv.y;
        Bs[lc + 2][lr] = bv.z; Bs[lc + 3][lr] = bv.w;
        __syncthreads();

#pragma unroll
        for (int kk = 0; kk < BK; kk++) {
            float ar[4], br[4];
#pragma unroll
            for (int i = 0; i < 4; i++) ar[i] = As[kk][ty * 4 + i];
#pragma unroll
            for (int j = 0; j < 4; j++) br[j] = Bs[kk][tx * 4 + j];
#pragma unroll
            for (int i = 0; i < 4; i++)
#pragma unroll
                for (int j = 0; j < 4; j++)
                    acc[i][j] = fmaf(ar[i], br[j], acc[i][j]);
        }
        __syncthreads();
    }

#pragma unroll
    for (int i = 0; i < 4; i++)
#pragma unroll
        for (int j = 0; j < 4; j++)
            ys[(size_t)(m0 + ty * 4 + i) * NO + n0 + tx * 4 + j] = acc[i][j];
}

extern "C" void kernel_launch(void* const* d_in, const int* in_sizes, int n_in,
                              void* d_out, int out_size)
{
    const float* x0 = (const float*)d_in[0];
    const float* t  = (const float*)d_in[1];
    const float* A  = (const float*)d_in[2];
    const float* C  = (const float*)d_in[3];
    float* out = (float*)d_out;

    // Reset all per-block flags (graph-replay safe).
    init_kernel<<<4, 256>>>();

    // ODE integration: xs = out[0 : NT*NS]
    ode_kernel<<<NBLK, NTHR>>>(x0, t, A, out);

    // Output projection: ys = out[NT*NS : ]
    dim3 g(NO / 64, NT / 64);
    gemm_ys<<<g, 256>>>(out, C, out + (size_t)NT * NS);

    // 4th launch: aligns ncu -s 5 -c 1 onto ode_kernel of the 2nd call.
    ncu_pad_kernel<<<1, 32>>>();
}